// round 2
// baseline (speedup 1.0000x reference)
#include <cuda_runtime.h>
#include <math.h>

#define Nn 16384
#define Dd 256
#define Ww 64
#define NC 1280   // cols: [0,256) q ; then 4 combined supports of 256 each

// Scratch (allocation-free rule: __device__ globals)
__device__ float g_B[Dd * NC];   // combined weight matrix [K=256, NC=1280]
__device__ float g_S[Nn * NC];   // per-row: q(256) | C_pred+same | C_pred+diff | C_suc+same | C_suc+diff

// ---------------------------------------------------------------------------
// Kernel 0: build combined weight matrix
// ---------------------------------------------------------------------------
__global__ void combine_kernel(const float* __restrict__ Wa,
                               const float* __restrict__ Wp,
                               const float* __restrict__ Wsuc,
                               const float* __restrict__ Wsame,
                               const float* __restrict__ Wdiff) {
    int idx = blockIdx.x * blockDim.x + threadIdx.x;
    if (idx >= Dd * NC) return;
    int e = idx / NC;
    int c = idx % NC;
    float v;
    if (c < 256) {
        v = Wa[e * 256 + c];
    } else {
        int k = (c - 256) >> 8;
        int d = c & 255;
        const float* A;
        const float* B;
        switch (k) {
            case 0:  A = Wp;   B = Wsame; break;  // pred + same
            case 1:  A = Wp;   B = Wdiff; break;  // pred + diff
            case 2:  A = Wsuc; B = Wsame; break;  // suc + same
            default: A = Wsuc; B = Wdiff; break;  // suc + diff
        }
        v = A[e * 256 + d] + B[e * 256 + d];
    }
    g_B[idx] = v;
}

// ---------------------------------------------------------------------------
// Kernel 1: SGEMM  g_S[16384,1280] = x[16384,256] @ g_B[256,1280]
// 128x128 tile, 8x8 per thread, BK=16
// ---------------------------------------------------------------------------
#define BM 128
#define BN 128
#define BK 16
#define TM 8
#define TN 8

__global__ __launch_bounds__(256, 2) void sgemm_kernel(const float* __restrict__ A) {
    __shared__ float As[BK][BM];
    __shared__ float Bs[BK][BN];
    const int K = Dd, N = NC;

    int bx = blockIdx.x;  // N tiles (10)
    int by = blockIdx.y;  // M tiles (128)
    int tid = threadIdx.x;

    const float* Ablk = A + (size_t)by * BM * K;
    const float* Bblk = g_B + bx * BN;
    float* Cblk = g_S + (size_t)by * BM * N + bx * BN;

    int aRow = tid >> 2;            // 0..63
    int aCol4 = (tid & 3) * 4;      // 0,4,8,12
    int bRow = tid >> 5;            // 0..7
    int bCol4 = (tid & 31) * 4;     // 0..124

    int tRow = (tid >> 4) * TM;
    int tCol = (tid & 15) * TN;

    float acc[TM][TN] = {};
    float regM[TM], regN[TN];

    for (int k0 = 0; k0 < K; k0 += BK) {
#pragma unroll
        for (int r = 0; r < 2; r++) {
            int row = aRow + r * 64;
            float4 v = *(const float4*)(Ablk + (size_t)row * K + k0 + aCol4);
            As[aCol4 + 0][row] = v.x;
            As[aCol4 + 1][row] = v.y;
            As[aCol4 + 2][row] = v.z;
            As[aCol4 + 3][row] = v.w;
        }
#pragma unroll
        for (int r = 0; r < 2; r++) {
            int row = bRow + r * 8;
            float4 v = *(const float4*)(Bblk + (size_t)(k0 + row) * N + bCol4);
            *(float4*)(&Bs[row][bCol4]) = v;
        }
        __syncthreads();
#pragma unroll
        for (int kk = 0; kk < BK; kk++) {
#pragma unroll
            for (int i = 0; i < TM; i++) regM[i] = As[kk][tRow + i];
#pragma unroll
            for (int j = 0; j < TN; j++) regN[j] = Bs[kk][tCol + j];
#pragma unroll
            for (int i = 0; i < TM; i++)
#pragma unroll
                for (int j = 0; j < TN; j++)
                    acc[i][j] += regM[i] * regN[j];
        }
        __syncthreads();
    }
#pragma unroll
    for (int i = 0; i < TM; i++) {
#pragma unroll
        for (int j = 0; j < TN; j += 4) {
            float4 v = make_float4(acc[i][j], acc[i][j + 1], acc[i][j + 2], acc[i][j + 3]);
            *(float4*)(Cblk + (size_t)(tRow + i) * N + tCol + j) = v;
        }
    }
}

// ---------------------------------------------------------------------------
// Kernel 2: per-utterance attention + banded aggregation + log_softmax
// one block (256 threads) per utterance n
// ---------------------------------------------------------------------------
__global__ __launch_bounds__(256) void attn_agg_kernel(const float* __restrict__ x,
                                                       const int* __restrict__ spk,
                                                       float* __restrict__ out) {
    int n = blockIdx.x;
    int tid = threadIdx.x;
    int lane = tid & 31, warp = tid >> 5;

    __shared__ float q_s[256];
    __shared__ float raw[128];
    __shared__ float aw[128];
    __shared__ int obase[128];
    __shared__ float s_red[8];
    __shared__ float s_m, s_z;

    q_s[tid] = g_S[(size_t)n * NC + tid];
    __syncthreads();

    // --- window dot products: raw[w] = x[n+w-64] . q[n]  (0 if out of range,
    //     matching the reference's zero-padded windows which still enter softmax)
    for (int slot = warp; slot < 128; slot += 8) {
        int j = n + slot - 64;
        float acc = 0.f;
        bool valid = (j >= 0) && (j < Nn);
        if (valid) {
            const float* xr = x + (size_t)j * 256;
#pragma unroll
            for (int t = 0; t < 8; t++)
                acc += xr[lane + 32 * t] * q_s[lane + 32 * t];
        }
#pragma unroll
        for (int o = 16; o > 0; o >>= 1)
            acc += __shfl_xor_sync(0xffffffffu, acc, o);
        if (lane == 0) raw[slot] = valid ? acc : 0.f;
    }
    __syncthreads();

    // --- softmax over all 128 slots (invalid slots have raw=0 and count in Z)
    if (warp == 0) {
        float v0 = raw[lane], v1 = raw[lane + 32], v2 = raw[lane + 64], v3 = raw[lane + 96];
        float m = fmaxf(fmaxf(v0, v1), fmaxf(v2, v3));
#pragma unroll
        for (int o = 16; o > 0; o >>= 1) m = fmaxf(m, __shfl_xor_sync(0xffffffffu, m, o));
        float z = expf(v0 - m) + expf(v1 - m) + expf(v2 - m) + expf(v3 - m);
#pragma unroll
        for (int o = 16; o > 0; o >>= 1) z += __shfl_xor_sync(0xffffffffu, z, o);
        if (lane == 0) { s_m = m; s_z = z; }
    }
    __syncthreads();

    int spk_n = spk[n];
    if (tid < 128) {
        int j = n + tid - 64;
        bool valid = (j >= 0) && (j < Nn);
        float a = 0.f;
        int ob = 0;
        if (valid) {
            a = expf(raw[tid] - s_m) / s_z;
            int diff = (spk[j] == spk_n) ? 0 : 1;        // same=0, diff=1
            int dir = (tid >= 64) ? 0 : 2;               // pred=0, suc=2
            ob = j * NC + 256 * (1 + dir + diff);
        }
        aw[tid] = a;
        obase[tid] = ob;
    }
    __syncthreads();

    // --- aggregation: one combined-support row read per valid slot (coalesced)
    float h = 0.f;
#pragma unroll 4
    for (int w = 0; w < 128; w++) {
        float a = aw[w];
        if (a != 0.f)
            h += a * g_S[(size_t)obase[w] + tid];
    }

    // --- log_softmax over D=256
    float m = h;
#pragma unroll
    for (int o = 16; o > 0; o >>= 1) m = fmaxf(m, __shfl_xor_sync(0xffffffffu, m, o));
    if (lane == 0) s_red[warp] = m;
    __syncthreads();
    if (warp == 0) {
        float mm = (lane < 8) ? s_red[lane] : -INFINITY;
#pragma unroll
        for (int o = 4; o > 0; o >>= 1) mm = fmaxf(mm, __shfl_xor_sync(0xffffffffu, mm, o));
        if (lane == 0) s_m = mm;
    }
    __syncthreads();
    float mfull = s_m;
    float e = expf(h - mfull);
    float z = e;
#pragma unroll
    for (int o = 16; o > 0; o >>= 1) z += __shfl_xor_sync(0xffffffffu, z, o);
    if (lane == 0) s_red[warp] = z;
    __syncthreads();
    if (warp == 0) {
        float zz = (lane < 8) ? s_red[lane] : 0.f;
#pragma unroll
        for (int o = 4; o > 0; o >>= 1) zz += __shfl_xor_sync(0xffffffffu, zz, o);
        if (lane == 0) s_z = zz;
    }
    __syncthreads();
    out[(size_t)n * 256 + tid] = h - mfull - logf(s_z);
}

// ---------------------------------------------------------------------------
extern "C" void kernel_launch(void* const* d_in, const int* in_sizes, int n_in,
                              void* d_out, int out_size) {
    const float* x     = (const float*)d_in[0];
    const int*   spk   = (const int*)d_in[1];
    const float* Wa    = (const float*)d_in[2];
    const float* Wp    = (const float*)d_in[3];
    const float* Wsuc  = (const float*)d_in[4];
    const float* Wsame = (const float*)d_in[5];
    const float* Wdiff = (const float*)d_in[6];
    float* out = (float*)d_out;

    combine_kernel<<<(Dd * NC + 255) / 256, 256>>>(Wa, Wp, Wsuc, Wsame, Wdiff);

    dim3 gg(NC / BN, Nn / BM);
    sgemm_kernel<<<gg, 256>>>(x);

    attn_agg_kernel<<<Nn, 256>>>(x, spk, out);
}